// round 16
// baseline (speedup 1.0000x reference)
#include <cuda_runtime.h>
#include <cstdint>
#include <math.h>

#define NB 128
#define NTOK 577
#define NP 576
#define DD 768
#define NG 17
#define NGC 18          // 17 groups + cls row
#define NOCC 10

typedef unsigned long long ull;

// ---- packed f32x2 helpers (sm_103a) ----
__device__ __forceinline__ ull pk2(float a, float b) {
    ull r; asm("mov.b64 %0, {%1,%2};" : "=l"(r) : "f"(a), "f"(b)); return r;
}
__device__ __forceinline__ void fma2(ull &acc, ull a, ull b) {
    asm("fma.rn.f32x2 %0, %1, %2, %0;" : "+l"(acc) : "l"(a), "l"(b));
}
__device__ __forceinline__ float hadd2(ull a) {
    return __uint_as_float((unsigned)a) + __uint_as_float((unsigned)(a >> 32));
}
__device__ __forceinline__ void cpasync16(uint32_t dst, const void* src) {
    asm volatile("cp.async.cg.shared.global [%0], [%1], 16;"
                 :: "r"(dst), "l"(src) : "memory");
}

// scratch (device global; no allocation). Holds MASKED attn after K1.
__device__ float g_scores[(size_t)NB * NG * NP];

// ================= K1: scores + sim + topk + softmax + attn ===============
// (unchanged from R7 — proven)
#define K1_THREADS 576
#define TILE_D 32
#define NT (DD / TILE_D)            // 24
#define PITCH 36                    // floats/row: conflict-free LDS.128
#define TILE_FLOATS (32 * PITCH)    // 1152
#define WPITCH 772                  // W row pitch: 9*772*4 % 128 = 16 (bank-split)
#define OFF_W  (18 * 2 * TILE_FLOATS)          // 41472
#define OFF_CD (OFF_W + NGC * WPITCH)          // 55368
#define K1_SMEM_FLOATS (OFF_CD + NP)           // 55944 floats = 223776 B

extern __shared__ float sm1[];

__global__ void __launch_bounds__(K1_THREADS, 1)
k1_scores(const float* __restrict__ x, const float* __restrict__ gw,
          float* __restrict__ out) {
    const int b   = blockIdx.x;
    const int tid = threadIdx.x;
    const int w   = tid >> 5, ln = tid & 31;
    const int li  = ln & 15,  h  = ln >> 4;
    float* s_w  = sm1 + OFF_W;
    float* s_cd = sm1 + OFF_CD;

    const size_t xb = (size_t)b * NTOK * DD;

    for (int i = tid; i < DD * NG; i += K1_THREADS) {
        int d = i / NG, g = i % NG;
        s_w[g * WPITCH + d] = gw[i];
    }
    for (int i = tid; i < DD; i += K1_THREADS) s_w[NG * WPITCH + i] = x[xb + i];

    const uint32_t smem_base = (uint32_t)__cvta_generic_to_shared(sm1);
    const uint32_t buf0 = smem_base + (uint32_t)(w * 2) * TILE_FLOATS * 4;
    const uint32_t buf1 = buf0 + TILE_FLOATS * 4;
    const float* xrow = x + xb + DD + (size_t)(w * 32) * DD;

#pragma unroll
    for (int t = 0; t < 2; ++t) {
        uint32_t dst = t ? buf1 : buf0;
        const float* src = xrow + t * TILE_D;
#pragma unroll
        for (int k = 0; k < 8; ++k) {
            int idx = ln + 32 * k;
            int row = idx >> 3, ch = idx & 7;
            cpasync16(dst + (uint32_t)(row * PITCH + ch * 4) * 4,
                      src + (size_t)row * DD + ch * 4);
        }
        asm volatile("cp.async.commit_group;" ::: "memory");
    }
    __syncthreads();

    ull a0[9], a1[9], nr0 = 0, nr1 = 0;
#pragma unroll
    for (int g = 0; g < 9; ++g) { a0[g] = 0; a1[g] = 0; }

    const float* wbase = s_w + h * 9 * WPITCH;

    for (int t = 0; t < NT; ++t) {
        asm volatile("cp.async.wait_group 1;" ::: "memory");
        __syncwarp();
        const float* xt  = sm1 + (size_t)(w * 2 + (t & 1)) * TILE_FLOATS;
        const float* wd0 = wbase + t * TILE_D;
#pragma unroll
        for (int blk = 0; blk < 8; ++blk) {
            ulonglong2 xv0 = *reinterpret_cast<const ulonglong2*>(
                xt + li * PITCH + blk * 4);
            ulonglong2 xv1 = *reinterpret_cast<const ulonglong2*>(
                xt + (li + 16) * PITCH + blk * 4);
            const float* wdb = wd0 + blk * 4;
#pragma unroll
            for (int gi = 0; gi < 9; ++gi) {
                ulonglong2 wv = *reinterpret_cast<const ulonglong2*>(wdb + gi * WPITCH);
                fma2(a0[gi], xv0.x, wv.x); fma2(a0[gi], xv0.y, wv.y);
                fma2(a1[gi], xv1.x, wv.x); fma2(a1[gi], xv1.y, wv.y);
            }
            fma2(nr0, xv0.x, xv0.x); fma2(nr0, xv0.y, xv0.y);
            fma2(nr1, xv1.x, xv1.x); fma2(nr1, xv1.y, xv1.y);
        }
        __syncwarp();
        if (t + 2 < NT) {
            uint32_t dst = (t & 1) ? buf1 : buf0;
            const float* src = xrow + (t + 2) * TILE_D;
#pragma unroll
            for (int k = 0; k < 8; ++k) {
                int idx = ln + 32 * k;
                int row = idx >> 3, ch = idx & 7;
                cpasync16(dst + (uint32_t)(row * PITCH + ch * 4) * 4,
                          src + (size_t)row * DD + ch * 4);
            }
        }
        asm volatile("cp.async.commit_group;" ::: "memory");
    }

    // epilogue: scores -> smem (tile region dead)
    __syncthreads();
    float* s_sc   = sm1;
    float* s_sim  = sm1 + NG * NP;
    float* s_mask = s_sim + NP;

    const int p0 = w * 32 + li, p1 = p0 + 16;
#pragma unroll
    for (int gi = 0; gi < 9; ++gi) {
        int g = h * 9 + gi;
        float v0 = hadd2(a0[gi]), v1 = hadd2(a1[gi]);
        if (g < NG) {
            s_sc[g * NP + p0] = v0;
            s_sc[g * NP + p1] = v1;
        } else {
            s_cd[p0] = v0;
            s_cd[p1] = v1;
        }
    }
    __syncthreads();
    if (h == 0) {
        // cls-norm factor dropped: positive per-batch constant, ordering-invariant
        s_sim[p0] = s_cd[p0] / fmaxf(sqrtf(hadd2(nr0)), 1e-12f);
        s_sim[p1] = s_cd[p1] / fmaxf(sqrtf(hadd2(nr1)), 1e-12f);
        s_mask[p0] = 1.0f; s_mask[p1] = 1.0f;
    }
    __syncthreads();

    if (tid < 32) {
        for (int k = 0; k < NOCC; ++k) {
            float best = 3.4e38f; int bi = NP;
#pragma unroll
            for (int q = 0; q < NP / 32; ++q) {
                int idx = tid + q * 32;
                float v = s_sim[idx];
                if (v < best || (v == best && idx < bi)) { best = v; bi = idx; }
            }
#pragma unroll
            for (int off = 16; off; off >>= 1) {
                float ov = __shfl_down_sync(0xffffffffu, best, off);
                int   oi = __shfl_down_sync(0xffffffffu, bi, off);
                if (ov < best || (ov == best && oi < bi)) { best = ov; bi = oi; }
            }
            bi = __shfl_sync(0xffffffffu, bi, 0);
            if (tid == 0) { s_sim[bi] = 3.4e38f; s_mask[bi] = 0.0f; }
            __syncwarp();
        }
    }
    __syncthreads();

    {
        const int p = tid;
        const float mk = s_mask[p];
        float tv[NG];
        float m = -3.4e38f;
#pragma unroll
        for (int g = 0; g < NG; ++g) {
            tv[g] = s_sc[g * NP + p] * 10.0f;
            m = fmaxf(m, tv[g]);
        }
        float ssum = 0.f;
#pragma unroll
        for (int g = 0; g < NG; ++g) { tv[g] = __expf(tv[g] - m); ssum += tv[g]; }
        const float inv = 1.0f / ssum;
        float* oat = out + (size_t)NB * NGC * DD + (size_t)b * NG * NP;
#pragma unroll
        for (int g = 0; g < NG; ++g) {
            float a = tv[g] * inv;
            oat[g * NP + p] = (mk != 0.f) ? a : (1.0f / 17.0f);
            g_scores[((size_t)b * NG + g) * NP + p] = (mk != 0.f) ? a : 0.f;
        }
    }
}

// ======================= K3: group features + cls =========================
// Flat grid 384, block 256, 3 CTAs/SM, reverse batch order (L2 reuse).
// R15 compute mapping (cols li/li+16, groups [9h,9h+9), padded attn halves).
// NEW: attn staged via cp.async (group 0, overlaps tile prologue);
//      4-stage x pipeline of 8-patch warp-private tiles (copy 3 tiles ahead).
#define K3_TP 8
#define K3_NT (NP / K3_TP)            // 72
#define WT_FLOATS (K3_TP * 32)        // 256 floats = 1 KB per buffer
#define NBUF 4
#define AT_HB (9 * NP + 4)            // half-block stride (16B bank shift)
#define K3_OFF_X (2 * 9 * NP + 4)     // 10372
#define K3_SMEM_FLOATS (K3_OFF_X + 8 * NBUF * WT_FLOATS)   // 18564 fl = 74256 B

extern __shared__ float sm3[];

__global__ void __launch_bounds__(256, 3)
k3_features(const float* __restrict__ x, float* __restrict__ out) {
    const int cid = blockIdx.x;
    const int b   = NB - 1 - cid / 3;       // reverse batch order (L2 reuse)
    const int y   = cid % 3;                // column slice
    const int tid = threadIdx.x;
    const int w   = tid >> 5, ln = tid & 31;
    const int li  = ln & 15,  h  = ln >> 4;
    float* s_at = sm3;
    float* wt0  = sm3 + K3_OFF_X + w * NBUF * WT_FLOATS;

    const size_t xb = (size_t)b * NTOK * DD;
    const float* xsrc = x + xb + DD + y * 256 + w * 32;   // patch 0

    const int d0 = y * 256 + w * 32 + li, d1 = d0 + 16;
    // hoisted cls loads (consumed in epilogue)
    const float cls0 = x[xb + d0], cls1 = x[xb + d1];

    const uint32_t at_base = (uint32_t)__cvta_generic_to_shared(s_at);
    const uint32_t wt_base = (uint32_t)__cvta_generic_to_shared(wt0);

    // ---- group 0: attn staging via cp.async (17 rows, 2448 16B chunks) ----
    {
        const float* gsrc = g_scores + (size_t)b * NG * NP;
#pragma unroll
        for (int k = 0; k < 10; ++k) {
            int idx = tid + 256 * k;
            if (idx < 2448) {
                int g = idx / 144, j = (idx - g * 144) * 4;   // 144 chunks/row
                int dstf = (g < 9 ? g * NP : AT_HB + (g - 9) * NP) + j;
                cpasync16(at_base + (uint32_t)dstf * 4, gsrc + (size_t)g * NP + j);
            }
        }
        asm volatile("cp.async.commit_group;" ::: "memory");
    }

    // ---- groups 1..3: tiles 0,1,2 ----
#pragma unroll
    for (int t = 0; t < 3; ++t) {
        uint32_t dst = wt_base + (uint32_t)t * WT_FLOATS * 4;
        const float* src = xsrc + (size_t)t * K3_TP * DD;
#pragma unroll
        for (int k = 0; k < 2; ++k) {
            int idx = ln + 32 * k;
            int row = idx >> 3, ch = idx & 7;
            cpasync16(dst + (uint32_t)(row * 32 + ch * 4) * 4,
                      src + (size_t)row * DD + ch * 4);
        }
        asm volatile("cp.async.commit_group;" ::: "memory");
    }

    // zero row (g=17) for h=1's padded 9th group
    for (int j = tid; j < NP; j += 256)
        s_at[AT_HB + 8 * NP + j] = 0.0f;

    // attn (group 0) + tile 0 complete; make visible to all warps
    asm volatile("cp.async.wait_group 2;" ::: "memory");
    __syncthreads();

    ull acc0[9], acc1[9];
#pragma unroll
    for (int g = 0; g < 9; ++g) { acc0[g] = 0; acc1[g] = 0; }

    const float* athalf = s_at + h * AT_HB;

    for (int t = 0; t < K3_NT; ++t) {
        if (t) { asm volatile("cp.async.wait_group 2;" ::: "memory"); }
        __syncwarp();
        const float* xt  = wt0 + (t & (NBUF - 1)) * WT_FLOATS;
        const float* at0 = athalf + t * K3_TP;
#pragma unroll
        for (int q = 0; q < K3_TP / 4; ++q) {     // q = 0,1 (4 patches each)
            const float* xq = xt + 4 * q * 32;
            float c00 = xq[0 * 32 + li],      c01 = xq[1 * 32 + li];
            float c02 = xq[2 * 32 + li],      c03 = xq[3 * 32 + li];
            float c10 = xq[0 * 32 + li + 16], c11 = xq[1 * 32 + li + 16];
            float c12 = xq[2 * 32 + li + 16], c13 = xq[3 * 32 + li + 16];
            ull x01c0 = pk2(c00, c01), x23c0 = pk2(c02, c03);
            ull x01c1 = pk2(c10, c11), x23c1 = pk2(c12, c13);
            const float* ap = at0 + 4 * q;
#pragma unroll
            for (int gi = 0; gi < 9; ++gi) {
                ulonglong2 at = *reinterpret_cast<const ulonglong2*>(ap + gi * NP);
                fma2(acc0[gi], x01c0, at.x); fma2(acc0[gi], x23c0, at.y);
                fma2(acc1[gi], x01c1, at.x); fma2(acc1[gi], x23c1, at.y);
            }
        }
        __syncwarp();
        if (t + 3 < K3_NT) {
            uint32_t dst = wt_base + (uint32_t)((t + 3) & (NBUF - 1)) * WT_FLOATS * 4;
            const float* src = xsrc + (size_t)(t + 3) * K3_TP * DD;
#pragma unroll
            for (int k = 0; k < 2; ++k) {
                int idx = ln + 32 * k;
                int row = idx >> 3, ch = idx & 7;
                cpasync16(dst + (uint32_t)(row * 32 + ch * 4) * 4,
                          src + (size_t)row * DD + ch * 4);
            }
        }
        asm volatile("cp.async.commit_group;" ::: "memory");
    }

    float* ob = out + (size_t)b * NGC * DD;
    if (h == 0) {
        ob[d0] = cls0;                        // feats[b][0][*] = cls
        ob[d1] = cls1;
#pragma unroll
        for (int gi = 0; gi < 9; ++gi) {      // groups 0..8
            ob[(size_t)(1 + gi) * DD + d0] = hadd2(acc0[gi]);
            ob[(size_t)(1 + gi) * DD + d1] = hadd2(acc1[gi]);
        }
    } else {
#pragma unroll
        for (int gi = 0; gi < 8; ++gi) {      // groups 9..16 (gi=8 is zero row)
            ob[(size_t)(1 + 9 + gi) * DD + d0] = hadd2(acc0[gi]);
            ob[(size_t)(1 + 9 + gi) * DD + d1] = hadd2(acc1[gi]);
        }
    }
}

extern "C" void kernel_launch(void* const* d_in, const int* in_sizes, int n_in,
                              void* d_out, int out_size) {
    const float* x  = (const float*)d_in[0];
    const float* gw = (const float*)d_in[1];
    float* out = (float*)d_out;

    static bool inited = false;
    if (!inited) {
        cudaFuncSetAttribute(k1_scores, cudaFuncAttributeMaxDynamicSharedMemorySize,
                             K1_SMEM_FLOATS * 4);
        cudaFuncSetAttribute(k3_features, cudaFuncAttributeMaxDynamicSharedMemorySize,
                             K3_SMEM_FLOATS * 4);
        inited = true;
    }

    k1_scores<<<NB, K1_THREADS, K1_SMEM_FLOATS * 4>>>(x, gw, out);
    k3_features<<<3 * NB, 256, K3_SMEM_FLOATS * 4>>>(x, out);
}

// round 17
// speedup vs baseline: 1.0602x; 1.0602x over previous
#include <cuda_runtime.h>
#include <cstdint>
#include <math.h>

#define NB 128
#define NTOK 577
#define NP 576
#define DD 768
#define NG 17
#define NGC 18          // 17 groups + cls row
#define NOCC 10

typedef unsigned long long ull;

// ---- packed f32x2 helpers (sm_103a) ----
__device__ __forceinline__ ull pk2(float a, float b) {
    ull r; asm("mov.b64 %0, {%1,%2};" : "=l"(r) : "f"(a), "f"(b)); return r;
}
__device__ __forceinline__ void fma2(ull &acc, ull a, ull b) {
    asm("fma.rn.f32x2 %0, %1, %2, %0;" : "+l"(acc) : "l"(a), "l"(b));
}
__device__ __forceinline__ float hadd2(ull a) {
    return __uint_as_float((unsigned)a) + __uint_as_float((unsigned)(a >> 32));
}
__device__ __forceinline__ void cpasync16(uint32_t dst, const void* src) {
    asm volatile("cp.async.cg.shared.global [%0], [%1], 16;"
                 :: "r"(dst), "l"(src) : "memory");
}

// scratch (device global; no allocation). Holds MASKED attn after K1.
__device__ float g_scores[(size_t)NB * NG * NP];

// ================= K1: scores + sim + topk + softmax + attn ===============
// (unchanged from R7 — proven)
#define K1_THREADS 576
#define TILE_D 32
#define NT (DD / TILE_D)            // 24
#define PITCH 36                    // floats/row: conflict-free LDS.128
#define TILE_FLOATS (32 * PITCH)    // 1152
#define WPITCH 772                  // W row pitch: 9*772*4 % 128 = 16 (bank-split)
#define OFF_W  (18 * 2 * TILE_FLOATS)          // 41472
#define OFF_CD (OFF_W + NGC * WPITCH)          // 55368
#define K1_SMEM_FLOATS (OFF_CD + NP)           // 55944 floats = 223776 B

extern __shared__ float sm1[];

__global__ void __launch_bounds__(K1_THREADS, 1)
k1_scores(const float* __restrict__ x, const float* __restrict__ gw,
          float* __restrict__ out) {
    const int b   = blockIdx.x;
    const int tid = threadIdx.x;
    const int w   = tid >> 5, ln = tid & 31;
    const int li  = ln & 15,  h  = ln >> 4;
    float* s_w  = sm1 + OFF_W;
    float* s_cd = sm1 + OFF_CD;

    const size_t xb = (size_t)b * NTOK * DD;

    for (int i = tid; i < DD * NG; i += K1_THREADS) {
        int d = i / NG, g = i % NG;
        s_w[g * WPITCH + d] = gw[i];
    }
    for (int i = tid; i < DD; i += K1_THREADS) s_w[NG * WPITCH + i] = x[xb + i];

    const uint32_t smem_base = (uint32_t)__cvta_generic_to_shared(sm1);
    const uint32_t buf0 = smem_base + (uint32_t)(w * 2) * TILE_FLOATS * 4;
    const uint32_t buf1 = buf0 + TILE_FLOATS * 4;
    const float* xrow = x + xb + DD + (size_t)(w * 32) * DD;

#pragma unroll
    for (int t = 0; t < 2; ++t) {
        uint32_t dst = t ? buf1 : buf0;
        const float* src = xrow + t * TILE_D;
#pragma unroll
        for (int k = 0; k < 8; ++k) {
            int idx = ln + 32 * k;
            int row = idx >> 3, ch = idx & 7;
            cpasync16(dst + (uint32_t)(row * PITCH + ch * 4) * 4,
                      src + (size_t)row * DD + ch * 4);
        }
        asm volatile("cp.async.commit_group;" ::: "memory");
    }
    __syncthreads();

    ull a0[9], a1[9], nr0 = 0, nr1 = 0;
#pragma unroll
    for (int g = 0; g < 9; ++g) { a0[g] = 0; a1[g] = 0; }

    const float* wbase = s_w + h * 9 * WPITCH;

    for (int t = 0; t < NT; ++t) {
        asm volatile("cp.async.wait_group 1;" ::: "memory");
        __syncwarp();
        const float* xt  = sm1 + (size_t)(w * 2 + (t & 1)) * TILE_FLOATS;
        const float* wd0 = wbase + t * TILE_D;
#pragma unroll
        for (int blk = 0; blk < 8; ++blk) {
            ulonglong2 xv0 = *reinterpret_cast<const ulonglong2*>(
                xt + li * PITCH + blk * 4);
            ulonglong2 xv1 = *reinterpret_cast<const ulonglong2*>(
                xt + (li + 16) * PITCH + blk * 4);
            const float* wdb = wd0 + blk * 4;
#pragma unroll
            for (int gi = 0; gi < 9; ++gi) {
                ulonglong2 wv = *reinterpret_cast<const ulonglong2*>(wdb + gi * WPITCH);
                fma2(a0[gi], xv0.x, wv.x); fma2(a0[gi], xv0.y, wv.y);
                fma2(a1[gi], xv1.x, wv.x); fma2(a1[gi], xv1.y, wv.y);
            }
            fma2(nr0, xv0.x, xv0.x); fma2(nr0, xv0.y, xv0.y);
            fma2(nr1, xv1.x, xv1.x); fma2(nr1, xv1.y, xv1.y);
        }
        __syncwarp();
        if (t + 2 < NT) {
            uint32_t dst = (t & 1) ? buf1 : buf0;
            const float* src = xrow + (t + 2) * TILE_D;
#pragma unroll
            for (int k = 0; k < 8; ++k) {
                int idx = ln + 32 * k;
                int row = idx >> 3, ch = idx & 7;
                cpasync16(dst + (uint32_t)(row * PITCH + ch * 4) * 4,
                          src + (size_t)row * DD + ch * 4);
            }
        }
        asm volatile("cp.async.commit_group;" ::: "memory");
    }

    // epilogue: scores -> smem (tile region dead)
    __syncthreads();
    float* s_sc   = sm1;
    float* s_sim  = sm1 + NG * NP;
    float* s_mask = s_sim + NP;

    const int p0 = w * 32 + li, p1 = p0 + 16;
#pragma unroll
    for (int gi = 0; gi < 9; ++gi) {
        int g = h * 9 + gi;
        float v0 = hadd2(a0[gi]), v1 = hadd2(a1[gi]);
        if (g < NG) {
            s_sc[g * NP + p0] = v0;
            s_sc[g * NP + p1] = v1;
        } else {
            s_cd[p0] = v0;
            s_cd[p1] = v1;
        }
    }
    __syncthreads();
    if (h == 0) {
        // cls-norm factor dropped: positive per-batch constant, ordering-invariant
        s_sim[p0] = s_cd[p0] / fmaxf(sqrtf(hadd2(nr0)), 1e-12f);
        s_sim[p1] = s_cd[p1] / fmaxf(sqrtf(hadd2(nr1)), 1e-12f);
        s_mask[p0] = 1.0f; s_mask[p1] = 1.0f;
    }
    __syncthreads();

    if (tid < 32) {
        for (int k = 0; k < NOCC; ++k) {
            float best = 3.4e38f; int bi = NP;
#pragma unroll
            for (int q = 0; q < NP / 32; ++q) {
                int idx = tid + q * 32;
                float v = s_sim[idx];
                if (v < best || (v == best && idx < bi)) { best = v; bi = idx; }
            }
#pragma unroll
            for (int off = 16; off; off >>= 1) {
                float ov = __shfl_down_sync(0xffffffffu, best, off);
                int   oi = __shfl_down_sync(0xffffffffu, bi, off);
                if (ov < best || (ov == best && oi < bi)) { best = ov; bi = oi; }
            }
            bi = __shfl_sync(0xffffffffu, bi, 0);
            if (tid == 0) { s_sim[bi] = 3.4e38f; s_mask[bi] = 0.0f; }
            __syncwarp();
        }
    }
    __syncthreads();

    {
        const int p = tid;
        const float mk = s_mask[p];
        float tv[NG];
        float m = -3.4e38f;
#pragma unroll
        for (int g = 0; g < NG; ++g) {
            tv[g] = s_sc[g * NP + p] * 10.0f;
            m = fmaxf(m, tv[g]);
        }
        float ssum = 0.f;
#pragma unroll
        for (int g = 0; g < NG; ++g) { tv[g] = __expf(tv[g] - m); ssum += tv[g]; }
        const float inv = 1.0f / ssum;
        float* oat = out + (size_t)NB * NGC * DD + (size_t)b * NG * NP;
#pragma unroll
        for (int g = 0; g < NG; ++g) {
            float a = tv[g] * inv;
            oat[g * NP + p] = (mk != 0.f) ? a : (1.0f / 17.0f);
            g_scores[((size_t)b * NG + g) * NP + p] = (mk != 0.f) ? a : 0.f;
        }
    }
}

// ======================= K3: group features + cls =========================
// R15 winner (16-patch double-buffered warp-private tiles, group-split
// compute, reverse batch order) + attn staged via cp.async group 0
// (overlaps tile prologue) + hoisted cls loads. Mainloop identical to R15.
#define K3_TP 16
#define K3_NT (NP / K3_TP)            // 36
#define WT_FLOATS (K3_TP * 32)        // 512 floats = 2 KB per buffer
#define AT_HB (9 * NP + 4)            // half-block stride (16B bank shift)
#define K3_OFF_X (2 * 9 * NP + 4)     // 10372
#define K3_SMEM_FLOATS (K3_OFF_X + 8 * 2 * WT_FLOATS)   // 18564 fl = 74256 B

extern __shared__ float sm3[];

__global__ void __launch_bounds__(256, 3)
k3_features(const float* __restrict__ x, float* __restrict__ out) {
    const int cid = blockIdx.x;
    const int b   = NB - 1 - cid / 3;       // reverse batch order (L2 reuse)
    const int y   = cid % 3;                // column slice
    const int tid = threadIdx.x;
    const int w   = tid >> 5, ln = tid & 31;
    const int li  = ln & 15,  h  = ln >> 4;
    float* s_at = sm3;
    float* wt0  = sm3 + K3_OFF_X + w * 2 * WT_FLOATS;

    const size_t xb = (size_t)b * NTOK * DD;
    const float* xsrc = x + xb + DD + y * 256 + w * 32;   // patch 0

    const int d0 = y * 256 + w * 32 + li, d1 = d0 + 16;
    const float cls0 = x[xb + d0], cls1 = x[xb + d1];     // hoisted

    const uint32_t at_base = (uint32_t)__cvta_generic_to_shared(s_at);
    const uint32_t wt_base = (uint32_t)__cvta_generic_to_shared(wt0);

    // group 0: attn staging via cp.async (17 rows = 2448 16B chunks)
    {
        const float* gsrc = g_scores + (size_t)b * NG * NP;
#pragma unroll
        for (int k = 0; k < 10; ++k) {
            int idx = tid + 256 * k;
            if (idx < 2448) {
                int g = idx / 144, j = (idx - g * 144) * 4;   // 144 chunks/row
                int dstf = (g < 9 ? g * NP : AT_HB + (g - 9) * NP) + j;
                cpasync16(at_base + (uint32_t)dstf * 4, gsrc + (size_t)g * NP + j);
            }
        }
        asm volatile("cp.async.commit_group;" ::: "memory");
    }

    // groups 1,2: tiles 0,1 (R15 16-patch tiles)
#pragma unroll
    for (int t = 0; t < 2; ++t) {
        uint32_t dst = wt_base + (uint32_t)t * WT_FLOATS * 4;
        const float* src = xsrc + (size_t)t * K3_TP * DD;
#pragma unroll
        for (int k = 0; k < 4; ++k) {
            int idx = ln + 32 * k;
            int row = idx >> 3, ch = idx & 7;
            cpasync16(dst + (uint32_t)(row * 32 + ch * 4) * 4,
                      src + (size_t)row * DD + ch * 4);
        }
        asm volatile("cp.async.commit_group;" ::: "memory");
    }

    // zero row (g=17) for h=1's padded 9th group
    for (int j = tid; j < NP; j += 256)
        s_at[AT_HB + 8 * NP + j] = 0.0f;

    // attn (g0) + tile0 (g1) complete; tile1 still in flight
    asm volatile("cp.async.wait_group 1;" ::: "memory");
    __syncthreads();

    ull acc0[9], acc1[9];
#pragma unroll
    for (int g = 0; g < 9; ++g) { acc0[g] = 0; acc1[g] = 0; }

    const float* athalf = s_at + h * AT_HB;

    for (int t = 0; t < K3_NT; ++t) {
        if (t) { asm volatile("cp.async.wait_group 1;" ::: "memory"); }
        __syncwarp();
        const float* xt  = wt0 + (t & 1) * WT_FLOATS;
        const float* at0 = athalf + t * K3_TP;
#pragma unroll
        for (int q = 0; q < K3_TP / 4; ++q) {
            const float* xq = xt + 4 * q * 32;
            float c00 = xq[0 * 32 + li],      c01 = xq[1 * 32 + li];
            float c02 = xq[2 * 32 + li],      c03 = xq[3 * 32 + li];
            float c10 = xq[0 * 32 + li + 16], c11 = xq[1 * 32 + li + 16];
            float c12 = xq[2 * 32 + li + 16], c13 = xq[3 * 32 + li + 16];
            ull x01c0 = pk2(c00, c01), x23c0 = pk2(c02, c03);
            ull x01c1 = pk2(c10, c11), x23c1 = pk2(c12, c13);
            const float* ap = at0 + 4 * q;
#pragma unroll
            for (int gi = 0; gi < 9; ++gi) {
                ulonglong2 at = *reinterpret_cast<const ulonglong2*>(ap + gi * NP);
                fma2(acc0[gi], x01c0, at.x); fma2(acc0[gi], x23c0, at.y);
                fma2(acc1[gi], x01c1, at.x); fma2(acc1[gi], x23c1, at.y);
            }
        }
        __syncwarp();
        if (t + 2 < K3_NT) {
            uint32_t dst = wt_base + (uint32_t)(t & 1) * WT_FLOATS * 4;
            const float* src = xsrc + (size_t)(t + 2) * K3_TP * DD;
#pragma unroll
            for (int k = 0; k < 4; ++k) {
                int idx = ln + 32 * k;
                int row = idx >> 3, ch = idx & 7;
                cpasync16(dst + (uint32_t)(row * 32 + ch * 4) * 4,
                          src + (size_t)row * DD + ch * 4);
            }
        }
        asm volatile("cp.async.commit_group;" ::: "memory");
    }

    float* ob = out + (size_t)b * NGC * DD;
    if (h == 0) {
        ob[d0] = cls0;                        // feats[b][0][*] = cls
        ob[d1] = cls1;
#pragma unroll
        for (int gi = 0; gi < 9; ++gi) {      // groups 0..8
            ob[(size_t)(1 + gi) * DD + d0] = hadd2(acc0[gi]);
            ob[(size_t)(1 + gi) * DD + d1] = hadd2(acc1[gi]);
        }
    } else {
#pragma unroll
        for (int gi = 0; gi < 8; ++gi) {      // groups 9..16 (gi=8 is zero row)
            ob[(size_t)(1 + 9 + gi) * DD + d0] = hadd2(acc0[gi]);
            ob[(size_t)(1 + 9 + gi) * DD + d1] = hadd2(acc1[gi]);
        }
    }
}

extern "C" void kernel_launch(void* const* d_in, const int* in_sizes, int n_in,
                              void* d_out, int out_size) {
    const float* x  = (const float*)d_in[0];
    const float* gw = (const float*)d_in[1];
    float* out = (float*)d_out;

    static bool inited = false;
    if (!inited) {
        cudaFuncSetAttribute(k1_scores, cudaFuncAttributeMaxDynamicSharedMemorySize,
                             K1_SMEM_FLOATS * 4);
        cudaFuncSetAttribute(k3_features, cudaFuncAttributeMaxDynamicSharedMemorySize,
                             K3_SMEM_FLOATS * 4);
        inited = true;
    }

    k1_scores<<<NB, K1_THREADS, K1_SMEM_FLOATS * 4>>>(x, gw, out);
    k3_features<<<3 * NB, 256, K3_SMEM_FLOATS * 4>>>(x, out);
}